// round 16
// baseline (speedup 1.0000x reference)
#include <cuda_runtime.h>
#include <cuda.h>
#include <cstdint>

// x: (8,16,2000,128) fp32. Per (b,c,f) column: POOL=10 block sums, causal
// cumulative mean/var over pooled blocks, normalize. Single pass.
//
// Grid = 1024 CTAs: (b*C+c) x (f-group QF=16), 128 threads. Ring NS=5 input
// tiles, each loaded by ONE cp.async.bulk.tensor.2d (TMA). R16: writes also
// go through TMA — phase C stores normalized values into a 2-stage smem out
// buffer (parity conflict-free), then one bulk tensor store per tile
// (bulk_group, <=1 outstanding). Store issue per tile drops 1280 STG -> 256
// STS + 1 TMA op; DRAM sees 5KB write bursts instead of warp-interleaved
// 64B fragments. Consume engine: parity bank-conflict-free register loads,
// distributed scan with ping-pong carry.

#define TT      2000
#define FF      128
#define PP      10
#define TT1     200
#define TB      8                    // pooled blocks per tile
#define NT      25                   // tiles
#define NS      5                    // input ring stages
#define QF      16                   // f-columns per CTA
#define ROWS    (TB * PP)            // 80 rows per tile
#define TILE_F  (ROWS * QF)          // 1280 floats
#define TILE_B  (TILE_F * 4)         // 5120 B
#define ROW_B   (FF * 4)             // 512 B global row stride
#define EPSV    1e-5f

__device__ __forceinline__ uint32_t s2u32(const void* p) {
    uint32_t a;
    asm("{ .reg .u64 t; cvta.to.shared.u64 t, %1; cvt.u32.u64 %0, t; }"
        : "=r"(a) : "l"(p));
    return a;
}
__device__ __forceinline__ void mbar_init(uint32_t m, uint32_t cnt) {
    asm volatile("mbarrier.init.shared.b64 [%0], %1;" :: "r"(m), "r"(cnt) : "memory");
}
__device__ __forceinline__ void mbar_expect_tx(uint32_t m, uint32_t bytes) {
    asm volatile("mbarrier.arrive.expect_tx.shared.b64 _, [%0], %1;"
                 :: "r"(m), "r"(bytes) : "memory");
}
__device__ __forceinline__ void mbar_wait(uint32_t m, uint32_t ph) {
    uint32_t done;
    asm volatile(
        "{\n\t.reg .pred p;\n\t"
        "mbarrier.try_wait.parity.acquire.cta.shared::cta.b64 p, [%1], %2;\n\t"
        "selp.b32 %0, 1, 0, p;\n\t}"
        : "=r"(done) : "r"(m), "r"(ph) : "memory");
    if (!done) {
        asm volatile(
            "{\n\t.reg .pred P1;\n\t"
            "W_%=:\n\t"
            "mbarrier.try_wait.parity.acquire.cta.shared::cta.b64 P1, [%0], %1, 0x989680;\n\t"
            "@P1 bra.uni D_%=;\n\t"
            "bra.uni W_%=;\n\t"
            "D_%=:\n\t}"
            :: "r"(m), "r"(ph) : "memory");
    }
}
__device__ __forceinline__ void tma_load_2d(uint32_t sdst, const void* tmap,
                                            int c0, int c1, uint32_t mbar) {
    asm volatile(
        "cp.async.bulk.tensor.2d.shared::cta.global.tile.mbarrier::complete_tx::bytes "
        "[%0], [%1, {%2, %3}], [%4];"
        :: "r"(sdst), "l"(tmap), "r"(c0), "r"(c1), "r"(mbar) : "memory");
}
__device__ __forceinline__ void tma_store_2d(const void* tmap, int c0, int c1,
                                             uint32_t ssrc) {
    asm volatile(
        "cp.async.bulk.tensor.2d.global.shared::cta.tile.bulk_group "
        "[%0, {%1, %2}], [%3];"
        :: "l"(tmap), "r"(c0), "r"(c1), "r"(ssrc) : "memory");
}
#define TMA_STORE_COMMIT() asm volatile("cp.async.bulk.commit_group;" ::: "memory")
#define TMA_STORE_WAIT(n)  asm volatile("cp.async.bulk.wait_group %0;" :: "n"(n) : "memory")

__global__ void __launch_bounds__(128)
inorm_kernel(const __grid_constant__ CUtensorMap tmapIn,
             const __grid_constant__ CUtensorMap tmapOut)
{
    __shared__ alignas(128) float ring[NS * TILE_F];     // 25600 B
    __shared__ alignas(128) float outSt[2][TILE_F];      // 10240 B
    __shared__ float2 bsArr[TB * QF];                    //  1024 B
    __shared__ float2 carry[2][QF];                      //   256 B
    __shared__ alignas(8) uint64_t mbarMem[NS];

    const int col = blockIdx.x >> 3;            // 0..127
    const int q   = blockIdx.x & 7;             // f-group of 16
    const int tid = threadIdx.x;
    const int b   = tid >> 4;                   // block within tile, 0..7
    const int f   = tid & 15;                   // f within group
    const int rp  = b & 1;                      // row-order parity (bank fix)

    const int c0    = q * QF;                   // inner coord (elements)
    const int rbase = col * TT;                 // row base for this column

    const uint32_t sring = s2u32(ring);
    const uint32_t mb    = s2u32(mbarMem);
    #define FULLB(s) (mb + (s) * 8)

    if (tid == 0) {
        #pragma unroll
        for (int s = 0; s < NS; s++) mbar_init(FULLB(s), 1);
    }
    if (tid < QF)
        carry[0][tid] = make_float2(0.f, 0.f);
    __syncthreads();
    asm volatile("fence.proxy.async.shared::cta;" ::: "memory");

    // Prologue: one TMA load per stage for tiles 0..NS-1
    if (tid == 0) {
        #pragma unroll
        for (int s = 0; s < NS; s++) {
            mbar_expect_tx(FULLB(s), TILE_B);
            tma_load_2d(sring + s * TILE_B, &tmapIn, c0, rbase + s * ROWS, FULLB(s));
        }
    }

    int st = 0, ph = 0;

    #pragma unroll 1
    for (int t = 0; t < NT; t++) {
        mbar_wait(FULLB(st), ph);
        __syncthreads();          // (1) tile visible to all; prev bsArr reads
                                  // done; tid0's store-wait (t-1) ordered in

        const float* tile = ring + st * TILE_F;

        // ── A: load my block's 10 rows once into registers, row order
        // i = (k+rp)%PP so half-warps hit opposite-parity rows (disjoint
        // bank sets); register index stays the constant k.
        float a[PP];
        {
            const float* base = tile + b * (PP * QF) + f;
            #pragma unroll
            for (int k = 0; k < PP; k++) {
                int i = k + rp; if (i == PP) i = 0;
                a[k] = base[i * QF];
            }
        }
        float bs = 0.f, bs2 = 0.f;
        #pragma unroll
        for (int k = 0; k < PP; k++) { bs += a[k]; bs2 = fmaf(a[k], a[k], bs2); }
        bsArr[b * QF + f] = make_float2(bs, bs2);
        __syncthreads();          // (2) bsArr ready; tile fully in regs

        // ── refill stage st with tile t+NS
        if (tid == 0) {
            const int tn = t + NS;
            if (tn < NT) {
                mbar_expect_tx(FULLB(st), TILE_B);
                tma_load_2d(sring + st * TILE_B, &tmapIn, c0,
                            rbase + tn * ROWS, FULLB(st));
            }
        }

        // ── B: distributed scan. thread (b,f) sums bsArr[0..b] + carry.
        float sA, s2A;
        {
            const float2 cc = carry[t & 1][f];
            sA = cc.x; s2A = cc.y;
            #pragma unroll
            for (int j = 0; j < TB; j++) {
                if (j <= b) {
                    const float2 v = bsArr[j * QF + f];
                    sA += v.x; s2A += v.y;
                }
            }
            if (b == TB - 1)
                carry[(t + 1) & 1][f] = make_float2(sA, s2A);
        }
        const float invn = __fdividef(1.0f, (float)((t * TB + b + 1) * PP));
        const float m    = sA * invn;
        const float var  = fmaf(-m, m, s2A * invn);
        const float r    = rsqrtf(var + EPSV);

        // ── C: normalize into smem out-stage (parity order, conflict-free)
        {
            float* ob = outSt[t & 1] + b * (PP * QF) + f;
            #pragma unroll
            for (int k = 0; k < PP; k++) {
                int i = k + rp; if (i == PP) i = 0;
                ob[i * QF] = (a[k] - m) * r;
            }
        }
        __syncthreads();          // (3) out-stage complete

        // ── one bulk tensor store per tile; keep <=1 outstanding so the
        // buffer written at t+2 (same parity) is already drained.
        if (tid == 0) {
            asm volatile("fence.proxy.async.shared::cta;" ::: "memory");
            tma_store_2d(&tmapOut, c0, rbase + t * ROWS,
                         s2u32(outSt[t & 1]));
            TMA_STORE_COMMIT();
            TMA_STORE_WAIT(1);
        }

        if (++st == NS) { st = 0; ph ^= 1; }
    }

    if (tid == 0) TMA_STORE_WAIT(0);   // drain before exit
}

typedef CUresult (*pfn_encode_t)(
    CUtensorMap*, CUtensorMapDataType, cuuint32_t, void*,
    const cuuint64_t*, const cuuint64_t*, const cuuint32_t*, const cuuint32_t*,
    CUtensorMapInterleave, CUtensorMapSwizzle, CUtensorMapL2promotion,
    CUtensorMapFloatOOBfill);

static void encode_map(pfn_encode_t enc, CUtensorMap* tm, void* base) {
    cuuint64_t dims[2]    = { (cuuint64_t)FF, (cuuint64_t)(128 * TT) };
    cuuint64_t strides[1] = { (cuuint64_t)ROW_B };
    cuuint32_t box[2]     = { QF, ROWS };          // 16 floats x 80 rows
    cuuint32_t estr[2]    = { 1, 1 };
    enc(tm, CU_TENSOR_MAP_DATA_TYPE_FLOAT32, 2, base,
        dims, strides, box, estr,
        CU_TENSOR_MAP_INTERLEAVE_NONE, CU_TENSOR_MAP_SWIZZLE_NONE,
        CU_TENSOR_MAP_L2_PROMOTION_L2_128B, CU_TENSOR_MAP_FLOAT_OOB_FILL_NONE);
}

extern "C" void kernel_launch(void* const* d_in, const int* in_sizes, int n_in,
                              void* d_out, int out_size)
{
    pfn_encode_t encode = nullptr;
    cudaDriverEntryPointQueryResult qr;
    cudaGetDriverEntryPoint("cuTensorMapEncodeTiled", (void**)&encode,
                            cudaEnableDefault, &qr);

    CUtensorMap tmIn, tmOut;
    encode_map(encode, &tmIn,  (void*)d_in[0]);
    encode_map(encode, &tmOut, d_out);

    inorm_kernel<<<1024, 128>>>(tmIn, tmOut);
}

// round 17
// speedup vs baseline: 1.0423x; 1.0423x over previous
#include <cuda_runtime.h>
#include <cuda.h>
#include <cstdint>

// x: (8,16,2000,128) fp32. Per (b,c,f) column: POOL=10 block sums, causal
// cumulative mean/var over pooled blocks, normalize. Single pass.
//
// R17 = R15 (best: TMA loads, scalar __stcs stores) +
//   (1) input tensor map L2_PROMOTION_256B: each 64B box-row fetch promotes
//       to 256B, covering 4 adjacent q-groups -> their CTAs hit L2 instead of
//       DRAM (working set ~5MB << 126MB L2). Deliberate 4-way read sharing.
//   (2) double-buffered bsArr: one __syncthreads per tile instead of two.
// Grid = 1024 CTAs ((b*C+c) x f-group QF=16), 128 threads, NS=5 TMA ring,
// parity bank-conflict-free register consume, distributed scan, __stcs out.

#define TT      2000
#define FF      128
#define PP      10
#define TT1     200
#define TB      8                    // pooled blocks per tile
#define NT      25                   // tiles
#define NS      5                    // ring stages
#define QF      16                   // f-columns per CTA
#define ROWS    (TB * PP)            // 80 rows per tile
#define TILE_F  (ROWS * QF)          // 1280 floats
#define TILE_B  (TILE_F * 4)         // 5120 B
#define ROW_B   (FF * 4)             // 512 B global row stride
#define EPSV    1e-5f

__device__ __forceinline__ uint32_t s2u32(const void* p) {
    uint32_t a;
    asm("{ .reg .u64 t; cvta.to.shared.u64 t, %1; cvt.u32.u64 %0, t; }"
        : "=r"(a) : "l"(p));
    return a;
}
__device__ __forceinline__ void mbar_init(uint32_t m, uint32_t cnt) {
    asm volatile("mbarrier.init.shared.b64 [%0], %1;" :: "r"(m), "r"(cnt) : "memory");
}
__device__ __forceinline__ void mbar_expect_tx(uint32_t m, uint32_t bytes) {
    asm volatile("mbarrier.arrive.expect_tx.shared.b64 _, [%0], %1;"
                 :: "r"(m), "r"(bytes) : "memory");
}
__device__ __forceinline__ void mbar_wait(uint32_t m, uint32_t ph) {
    uint32_t done;
    asm volatile(
        "{\n\t.reg .pred p;\n\t"
        "mbarrier.try_wait.parity.acquire.cta.shared::cta.b64 p, [%1], %2;\n\t"
        "selp.b32 %0, 1, 0, p;\n\t}"
        : "=r"(done) : "r"(m), "r"(ph) : "memory");
    if (!done) {
        asm volatile(
            "{\n\t.reg .pred P1;\n\t"
            "W_%=:\n\t"
            "mbarrier.try_wait.parity.acquire.cta.shared::cta.b64 P1, [%0], %1, 0x989680;\n\t"
            "@P1 bra.uni D_%=;\n\t"
            "bra.uni W_%=;\n\t"
            "D_%=:\n\t}"
            :: "r"(m), "r"(ph) : "memory");
    }
}
__device__ __forceinline__ void tma_load_2d(uint32_t sdst, const void* tmap,
                                            int c0, int c1, uint32_t mbar) {
    asm volatile(
        "cp.async.bulk.tensor.2d.shared::cta.global.tile.mbarrier::complete_tx::bytes "
        "[%0], [%1, {%2, %3}], [%4];"
        :: "r"(sdst), "l"(tmap), "r"(c0), "r"(c1), "r"(mbar) : "memory");
}

__global__ void __launch_bounds__(128)
inorm_kernel(const __grid_constant__ CUtensorMap tmap, float* __restrict__ out)
{
    __shared__ alignas(128) float ring[NS * TILE_F];   // 25600 B
    __shared__ float2 bsArr[2][TB * QF];               //  2048 B (double buf)
    __shared__ float2 carry[2][QF];                    //   256 B
    __shared__ alignas(8) uint64_t mbarMem[NS];

    const int col = blockIdx.x >> 3;            // 0..127
    const int q   = blockIdx.x & 7;             // f-group of 16
    const int tid = threadIdx.x;
    const int b   = tid >> 4;                   // block within tile, 0..7
    const int f   = tid & 15;                   // f within group
    const int rp  = b & 1;                      // row-order parity (bank fix)

    const int c0    = q * QF;                   // inner coord (elements)
    const int rbase = col * TT;                 // row base for this column

    char* oq = (char*)(out + (size_t)col * (TT * FF) + q * QF);

    const uint32_t sring = s2u32(ring);
    const uint32_t mb    = s2u32(mbarMem);
    #define FULLB(s) (mb + (s) * 8)

    if (tid == 0) {
        #pragma unroll
        for (int s = 0; s < NS; s++) mbar_init(FULLB(s), 1);
    }
    if (tid < QF)
        carry[0][tid] = make_float2(0.f, 0.f);
    __syncthreads();
    asm volatile("fence.proxy.async.shared::cta;" ::: "memory");

    // Prologue: one TMA per stage for tiles 0..NS-1
    if (tid == 0) {
        #pragma unroll
        for (int s = 0; s < NS; s++) {
            mbar_expect_tx(FULLB(s), TILE_B);
            tma_load_2d(sring + s * TILE_B, &tmap, c0, rbase + s * ROWS, FULLB(s));
        }
    }

    int st = 0, ph = 0;

    #pragma unroll 1
    for (int t = 0; t < NT; t++) {
        mbar_wait(FULLB(st), ph);     // every thread waits; tile st visible

        const float* tile = ring + st * TILE_F;
        float2* bsw = bsArr[t & 1];

        // ── A: load my block's 10 rows once into registers, row order
        // i = (k+rp)%PP (half-warps on opposite-parity rows, no conflicts);
        // register index stays the constant k.
        float a[PP];
        {
            const float* base = tile + b * (PP * QF) + f;
            #pragma unroll
            for (int k = 0; k < PP; k++) {
                int i = k + rp; if (i == PP) i = 0;
                a[k] = base[i * QF];
            }
        }
        float bs = 0.f, bs2 = 0.f;
        #pragma unroll
        for (int k = 0; k < PP; k++) { bs += a[k]; bs2 = fmaf(a[k], a[k], bs2); }
        bsw[b * QF + f] = make_float2(bs, bs2);
        __syncthreads();              // (only barrier) bsArr[t&1] ready;
                                      // tile fully consumed to registers

        // ── refill stage st with tile t+NS
        if (tid == 0) {
            const int tn = t + NS;
            if (tn < NT) {
                mbar_expect_tx(FULLB(st), TILE_B);
                tma_load_2d(sring + st * TILE_B, &tmap, c0,
                            rbase + tn * ROWS, FULLB(st));
            }
        }

        // ── B: distributed scan. thread (b,f) sums bsArr[t&1][0..b] + carry.
        float sA, s2A;
        {
            const float2 cc = carry[t & 1][f];
            sA = cc.x; s2A = cc.y;
            #pragma unroll
            for (int j = 0; j < TB; j++) {
                if (j <= b) {
                    const float2 v = bsw[j * QF + f];
                    sA += v.x; s2A += v.y;
                }
            }
            if (b == TB - 1)
                carry[(t + 1) & 1][f] = make_float2(sA, s2A);
        }
        const float invn = __fdividef(1.0f, (float)((t * TB + b + 1) * PP));
        const float m    = sA * invn;
        const float var  = fmaf(-m, m, s2A * invn);
        const float r    = rsqrtf(var + EPSV);

        // ── C: normalize from registers; a[k] goes back to ITS row i.
        {
            char* og = oq + (size_t)(t * ROWS + b * PP) * ROW_B + f * 4;
            #pragma unroll
            for (int k = 0; k < PP; k++) {
                int i = k + rp; if (i == PP) i = 0;
                __stcs((float*)(og + (size_t)i * ROW_B), (a[k] - m) * r);
            }
        }

        if (++st == NS) { st = 0; ph ^= 1; }
    }
}

typedef CUresult (*pfn_encode_t)(
    CUtensorMap*, CUtensorMapDataType, cuuint32_t, void*,
    const cuuint64_t*, const cuuint64_t*, const cuuint32_t*, const cuuint32_t*,
    CUtensorMapInterleave, CUtensorMapSwizzle, CUtensorMapL2promotion,
    CUtensorMapFloatOOBfill);

extern "C" void kernel_launch(void* const* d_in, const int* in_sizes, int n_in,
                              void* d_out, int out_size)
{
    const float* x   = (const float*)d_in[0];
    float*       out = (float*)d_out;

    pfn_encode_t encode = nullptr;
    cudaDriverEntryPointQueryResult qr;
    cudaGetDriverEntryPoint("cuTensorMapEncodeTiled", (void**)&encode,
                            cudaEnableDefault, &qr);

    // x viewed as 2D: inner = 128 floats (F), rows = 128 cols * 2000 t.
    // L2 promotion 256B: one fetch covers 4 q-groups -> 4-way L2 read sharing.
    CUtensorMap tmap;
    cuuint64_t dims[2]    = { (cuuint64_t)FF, (cuuint64_t)(128 * TT) };
    cuuint64_t strides[1] = { (cuuint64_t)ROW_B };
    cuuint32_t box[2]     = { QF, ROWS };          // 16 floats x 80 rows
    cuuint32_t estr[2]    = { 1, 1 };
    encode(&tmap, CU_TENSOR_MAP_DATA_TYPE_FLOAT32, 2, (void*)x,
           dims, strides, box, estr,
           CU_TENSOR_MAP_INTERLEAVE_NONE, CU_TENSOR_MAP_SWIZZLE_NONE,
           CU_TENSOR_MAP_L2_PROMOTION_L2_256B, CU_TENSOR_MAP_FLOAT_OOB_FILL_NONE);

    inorm_kernel<<<1024, 128>>>(tmap, out);
}